// round 15
// baseline (speedup 1.0000x reference)
#include <cuda_runtime.h>

// ---------------- problem constants ----------------
#define NNODE 100000
#define NEDGE 500000
#define G3    768     // 3 * HID
#define HID   256
#define NH    8
#define ODIM  64

// ---------------- device scratch (allowed: __device__ globals) ----------------
__device__ float d_gif[(size_t)NNODE * G3];   // per-node gi forward  (incl b_ih)
__device__ float d_gib[(size_t)NNODE * G3];   // per-node gi backward
__device__ float d_h1f[(size_t)NNODE * HID];  // per-node first-step hidden, fwd
__device__ float d_h1b[(size_t)NNODE * HID];  // per-node first-step hidden, bwd
__device__ float d_Hf[(size_t)NEDGE * HID];   // per-edge hidden, fwd
__device__ float d_Hb[(size_t)NEDGE * HID];   // per-edge hidden, bwd
__device__ float d_GH[(size_t)NEDGE * G3];    // gh scratch (reused each step)
__device__ float d_Alog[(size_t)NEDGE * NH];  // logits -> exp values
__device__ float d_Mmax[(size_t)NNODE * NH];  // segment max
__device__ float d_Den[(size_t)NNODE * NH];   // segment denom

// ---------------- helpers ----------------
union F2U { float2 f; unsigned long long u; };

#define FMA2(c, a, b) asm("fma.rn.f32x2 %0, %1, %2, %0;" : "+l"(c) : "l"(a), "l"(b))

__device__ __forceinline__ float sigf(float x) {
    return 1.0f / (1.0f + __expf(-x));
}

__device__ __forceinline__ void atomicMaxFloat(float* addr, float v) {
    // standard trick: signed max for non-negative, unsigned min for negative
    if (v >= 0.0f) atomicMax((int*)addr, __float_as_int(v));
    else           atomicMin((unsigned int*)addr, __float_as_uint(v));
}

// ---------------- GEMM: C[M x 768] = A[M x K] @ W[768 x K]^T (+ bias) ----------------
// Block: 128 rows x 64 cols, BK=16, 256 threads, per-thread 8m x 4n with
// f32x2 accumulators paired over M. W stored duplicated in smem (no inner packs).
template <int K>
__global__ __launch_bounds__(256) void gemm768(
    const float* __restrict__ A, const float* __restrict__ W,
    const float* __restrict__ bias, float* __restrict__ C, int M)
{
    __shared__ unsigned long long Ws[16][64];  // W value duplicated into both lanes
    __shared__ float As[16][128];              // A transposed: [k][m]

    const int tid = threadIdx.x;
    const int rowBase = blockIdx.y * 128;
    const int colBase = blockIdx.x * 64;
    const int tx = tid & 15;          // column group
    const int ty = tid >> 4;          // row group
    const int m0 = ty * 8;            // 8 rows per thread (4 f32x2 pairs)
    // columns handled: colBase + tx + 16*i  (stride-16 -> conflict-free LDS.64)
    const int lm = tid >> 2;          // loader row / W row (0..63)
    const int lk = (tid & 3) * 4;     // loader k offset

    unsigned long long acc[4][4];
#pragma unroll
    for (int i = 0; i < 4; i++)
#pragma unroll
        for (int j = 0; j < 4; j++) acc[i][j] = 0ULL;

    const float* wp = W + (size_t)(colBase + lm) * K + lk;

    for (int k0 = 0; k0 < K; k0 += 16) {
        // --- load A tile (two row passes), transposed into smem ---
#pragma unroll
        for (int p = 0; p < 2; p++) {
            int r = rowBase + lm + p * 64;
            float4 v = make_float4(0.f, 0.f, 0.f, 0.f);
            if (r < M) v = *reinterpret_cast<const float4*>(A + (size_t)r * K + k0 + lk);
            As[lk + 0][lm + p * 64] = v.x;
            As[lk + 1][lm + p * 64] = v.y;
            As[lk + 2][lm + p * 64] = v.z;
            As[lk + 3][lm + p * 64] = v.w;
        }
        // --- load W tile, store duplicated pairs ---
        {
            float4 v = *reinterpret_cast<const float4*>(wp + k0);
            F2U u;
            u.f = make_float2(v.x, v.x); Ws[lk + 0][lm] = u.u;
            u.f = make_float2(v.y, v.y); Ws[lk + 1][lm] = u.u;
            u.f = make_float2(v.z, v.z); Ws[lk + 2][lm] = u.u;
            u.f = make_float2(v.w, v.w); Ws[lk + 3][lm] = u.u;
        }
        __syncthreads();
#pragma unroll
        for (int kk = 0; kk < 16; kk++) {
            unsigned long long b0 = Ws[kk][tx];
            unsigned long long b1 = Ws[kk][tx + 16];
            unsigned long long b2 = Ws[kk][tx + 32];
            unsigned long long b3 = Ws[kk][tx + 48];
            const unsigned long long* ap =
                reinterpret_cast<const unsigned long long*>(&As[kk][m0]);
            unsigned long long a0 = ap[0], a1 = ap[1], a2 = ap[2], a3 = ap[3];
            FMA2(acc[0][0], a0, b0); FMA2(acc[0][1], a0, b1);
            FMA2(acc[0][2], a0, b2); FMA2(acc[0][3], a0, b3);
            FMA2(acc[1][0], a1, b0); FMA2(acc[1][1], a1, b1);
            FMA2(acc[1][2], a1, b2); FMA2(acc[1][3], a1, b3);
            FMA2(acc[2][0], a2, b0); FMA2(acc[2][1], a2, b1);
            FMA2(acc[2][2], a2, b2); FMA2(acc[2][3], a2, b3);
            FMA2(acc[3][0], a3, b0); FMA2(acc[3][1], a3, b1);
            FMA2(acc[3][2], a3, b2); FMA2(acc[3][3], a3, b3);
        }
        __syncthreads();
    }

    // --- epilogue ---
    float bv[4] = {0.f, 0.f, 0.f, 0.f};
    if (bias) {
#pragma unroll
        for (int i = 0; i < 4; i++) bv[i] = bias[colBase + tx + 16 * i];
    }
#pragma unroll
    for (int mp = 0; mp < 4; mp++) {
        int r = rowBase + m0 + mp * 2;
#pragma unroll
        for (int i = 0; i < 4; i++) {
            F2U u; u.u = acc[mp][i];
            int col = colBase + tx + 16 * i;
            if (r < M)     C[(size_t)r       * G3 + col] = u.f.x + bv[i];
            if (r + 1 < M) C[(size_t)(r + 1) * G3 + col] = u.f.y + bv[i];
        }
    }
}

// ---------------- per-node first-step hidden (h0 = 0) ----------------
__global__ void h1_kernel(const float* __restrict__ gif, const float* __restrict__ gib,
                          const float* __restrict__ bhf, const float* __restrict__ bhb,
                          float* __restrict__ h1f, float* __restrict__ h1b)
{
    int n = blockIdx.x, t = threadIdx.x;
    size_t g = (size_t)n * G3;
    {
        float r  = sigf(gif[g + t]       + bhf[t]);
        float z  = sigf(gif[g + 256 + t] + bhf[256 + t]);
        float nn = tanhf(gif[g + 512 + t] + r * bhf[512 + t]);
        h1f[(size_t)n * HID + t] = (1.0f - z) * nn;
    }
    {
        float r  = sigf(gib[g + t]       + bhb[t]);
        float z  = sigf(gib[g + 256 + t] + bhb[256 + t]);
        float nn = tanhf(gib[g + 512 + t] + r * bhb[512 + t]);
        h1b[(size_t)n * HID + t] = (1.0f - z) * nn;
    }
}

// ---------------- gather initial hidden per edge ----------------
__global__ void hinit_kernel(float* __restrict__ H, const float* __restrict__ h1,
                             const int* __restrict__ emi, int col)
{
    int e = blockIdx.x, t = threadIdx.x;
    int node = emi[e * 4 + col];
    H[(size_t)e * HID + t] = h1[(size_t)node * HID + t];
}

// ---------------- GRU pointwise step (gi gathered per node; biases pre-folded) ----------------
// GI includes b_ih (GEMM bias); GH includes b_hh (GEMM bias).
__global__ void gru_step(float* __restrict__ H, const float* __restrict__ GH,
                         const float* __restrict__ GI, const int* __restrict__ emi, int col)
{
    int e = blockIdx.x, t = threadIdx.x;
    int node = emi[e * 4 + col];
    size_t ge = (size_t)e * G3, gn = (size_t)node * G3;
    float r  = sigf(GI[gn + t]       + GH[ge + t]);
    float z  = sigf(GI[gn + 256 + t] + GH[ge + 256 + t]);
    float nn = tanhf(GI[gn + 512 + t] + r * GH[ge + 512 + t]);
    size_t hi = (size_t)e * HID + t;
    float h = H[hi];
    H[hi] = (1.0f - z) * nn + z * h;
}

// ---------------- init segment max / denom ----------------
__global__ void init_md(float* __restrict__ Mmax, float* __restrict__ Den)
{
    int i = blockIdx.x * 256 + threadIdx.x;  // exactly NNODE*NH threads
    Mmax[i] = __int_as_float(0xFF800000);    // -inf
    Den[i] = 0.0f;
}

// ---------------- attention logits + leaky relu + segment max ----------------
// eft[e,h,d] = (d<32) ? Hf[e][d*8+h] : Hb[e][(d-32)*8+h]
__global__ void attn_kernel(const float* __restrict__ Hf, const float* __restrict__ Hb,
                            const float* __restrict__ attn, const int* __restrict__ dst,
                            float* __restrict__ Alog, float* __restrict__ Mmax)
{
    __shared__ float at[512];
    int tid = threadIdx.x;
    at[tid] = attn[tid];
    at[tid + 256] = attn[tid + 256];
    __syncthreads();

    int eL = tid >> 3, h = tid & 7;
    int e = blockIdx.x * 32 + eL;
    const float* hf = Hf + (size_t)e * HID;
    const float* hb = Hb + (size_t)e * HID;
    float acc = 0.0f;
#pragma unroll
    for (int d = 0; d < 32; d++) acc += hf[d * 8 + h] * at[h * 64 + d];
#pragma unroll
    for (int d = 0; d < 32; d++) acc += hb[d * 8 + h] * at[h * 64 + 32 + d];
    float a = (acc >= 0.0f) ? acc : 0.01f * acc;
    Alog[(size_t)e * NH + h] = a;
    atomicMaxFloat(&Mmax[(size_t)dst[e] * NH + h], a);
}

// ---------------- exp + segment denom ----------------
__global__ void expden_kernel(const int* __restrict__ dst, float* __restrict__ Alog,
                              const float* __restrict__ Mmax, float* __restrict__ Den)
{
    int i = blockIdx.x * 256 + threadIdx.x;  // exactly NEDGE*NH threads
    int e = i >> 3, h = i & 7;
    int d = dst[e];
    float ex = __expf(Alog[i] - Mmax[(size_t)d * NH + h]);
    Alog[i] = ex;
    atomicAdd(&Den[(size_t)d * NH + h], ex);
}

// ---------------- weighted scatter into destination nodes ----------------
__global__ void scatter_kernel(const float* __restrict__ Hf, const float* __restrict__ Hb,
                               const float* __restrict__ Alog, const float* __restrict__ Den,
                               const int* __restrict__ dst, float* __restrict__ out)
{
    int warp = threadIdx.x >> 5, lane = threadIdx.x & 31;
    int e = blockIdx.x * 8 + warp;
    int h = lane >> 2;
    int dq = (lane & 3) << 4;  // 0,16,32,48
    int dn = dst[e];
    float w = Alog[(size_t)e * NH + h] / Den[(size_t)dn * NH + h];
    float* ob = out + (size_t)dn * (NH * ODIM) + h * ODIM + dq;
    const float* src = (dq < 32)
        ? (Hf + (size_t)e * HID + dq * 8 + h)
        : (Hb + (size_t)e * HID + (dq - 32) * 8 + h);
#pragma unroll
    for (int i = 0; i < 16; i++) atomicAdd(ob + i, src[i * 8] * w);
}

// ---------------- launch ----------------
extern "C" void kernel_launch(void* const* d_in, const int* in_sizes, int n_in,
                              void* d_out, int out_size)
{
    const float* features = (const float*)d_in[0];
    const float* w_ih_f   = (const float*)d_in[1];
    const float* w_hh_f   = (const float*)d_in[2];
    const float* b_ih_f   = (const float*)d_in[3];
    const float* b_hh_f   = (const float*)d_in[4];
    const float* w_ih_b   = (const float*)d_in[5];
    const float* w_hh_b   = (const float*)d_in[6];
    const float* b_ih_b   = (const float*)d_in[7];
    const float* b_hh_b   = (const float*)d_in[8];
    const float* attn     = (const float*)d_in[9];
    const int*   emi      = (const int*)d_in[10];
    const int*   edst     = (const int*)d_in[11];
    float* out = (float*)d_out;

    float *gif, *gib, *h1f, *h1b, *Hf, *Hb, *GH, *Alog, *Mmax, *Den;
    cudaGetSymbolAddress((void**)&gif,  d_gif);
    cudaGetSymbolAddress((void**)&gib,  d_gib);
    cudaGetSymbolAddress((void**)&h1f,  d_h1f);
    cudaGetSymbolAddress((void**)&h1b,  d_h1b);
    cudaGetSymbolAddress((void**)&Hf,   d_Hf);
    cudaGetSymbolAddress((void**)&Hb,   d_Hb);
    cudaGetSymbolAddress((void**)&GH,   d_GH);
    cudaGetSymbolAddress((void**)&Alog, d_Alog);
    cudaGetSymbolAddress((void**)&Mmax, d_Mmax);
    cudaGetSymbolAddress((void**)&Den,  d_Den);

    // zero output (poisoned by harness) + init segment buffers
    cudaMemsetAsync(d_out, 0, (size_t)out_size * sizeof(float), 0);
    init_md<<<(NNODE * NH) / 256, 256>>>(Mmax, Den);

    // per-node gi (input transform + b_ih) and first-step hidden
    dim3 gn(G3 / 64, (NNODE + 127) / 128);
    gemm768<64><<<gn, 256>>>(features, w_ih_f, b_ih_f, gif, NNODE);
    gemm768<64><<<gn, 256>>>(features, w_ih_b, b_ih_b, gib, NNODE);
    h1_kernel<<<NNODE, 256>>>(gif, gib, b_hh_f, b_hh_b, h1f, h1b);

    dim3 ge(G3 / 64, (NEDGE + 127) / 128);

    // forward direction: inputs are metapath cols 0,1,2,3 (step 1 precomputed)
    hinit_kernel<<<NEDGE, 256>>>(Hf, h1f, emi, 0);
    for (int t = 1; t <= 3; t++) {
        gemm768<256><<<ge, 256>>>(Hf, w_hh_f, b_hh_f, GH, NEDGE);
        gru_step<<<NEDGE, 256>>>(Hf, GH, gif, emi, t);
    }

    // backward direction: inputs are cols 3,2,1,0 (step 1 precomputed from col 3)
    hinit_kernel<<<NEDGE, 256>>>(Hb, h1b, emi, 3);
    const int bcols[3] = {2, 1, 0};
    for (int t = 0; t < 3; t++) {
        gemm768<256><<<ge, 256>>>(Hb, w_hh_b, b_hh_b, GH, NEDGE);
        gru_step<<<NEDGE, 256>>>(Hb, GH, gib, emi, bcols[t]);
    }

    // attention + segment softmax + scatter
    attn_kernel<<<NEDGE / 32, 256>>>(Hf, Hb, attn, edst, Alog, Mmax);
    expden_kernel<<<(NEDGE * NH) / 256, 256>>>(edst, Alog, Mmax, Den);
    scatter_kernel<<<NEDGE / 8, 256>>>(Hf, Hb, Alog, Den, edst, out);
}

// round 16
// speedup vs baseline: 1.7573x; 1.7573x over previous
#include <cuda_runtime.h>
#include <cuda_bf16.h>

// ---------------- problem constants ----------------
#define NNODE 100000
#define NEDGE 500000
#define G3    768     // 3 * HID
#define HID   256
#define NH    8
#define ODIM  64
#define LDT   40      // smem row stride (bf16 elems): 80B -> conflict-free LDSM

// ---------------- device scratch ----------------
__device__ float d_gif[(size_t)NNODE * G3];
__device__ float d_gib[(size_t)NNODE * G3];
__device__ float d_h1f[(size_t)NNODE * HID];
__device__ float d_h1b[(size_t)NNODE * HID];
__device__ float d_Hf[(size_t)NEDGE * HID];
__device__ float d_Hb[(size_t)NEDGE * HID];
__device__ float d_GH[(size_t)NEDGE * G3];
__device__ float d_Alog[(size_t)NEDGE * NH];
__device__ float d_Mmax[(size_t)NNODE * NH];
__device__ float d_Den[(size_t)NNODE * NH];
// split-bf16 operands
__device__ __nv_bfloat16 d_Hhi[(size_t)NEDGE * HID];
__device__ __nv_bfloat16 d_Hlo[(size_t)NEDGE * HID];
__device__ __nv_bfloat16 d_Fhi[(size_t)NNODE * ODIM];
__device__ __nv_bfloat16 d_Flo[(size_t)NNODE * ODIM];
__device__ __nv_bfloat16 d_WihfHi[G3 * ODIM], d_WihfLo[G3 * ODIM];
__device__ __nv_bfloat16 d_WihbHi[G3 * ODIM], d_WihbLo[G3 * ODIM];
__device__ __nv_bfloat16 d_WhhfHi[G3 * HID], d_WhhfLo[G3 * HID];
__device__ __nv_bfloat16 d_WhhbHi[G3 * HID], d_WhhbLo[G3 * HID];

// ---------------- helpers ----------------
__device__ __forceinline__ float sigf(float x) { return 1.0f / (1.0f + __expf(-x)); }

__device__ __forceinline__ void atomicMaxFloat(float* addr, float v) {
    if (v >= 0.0f) atomicMax((int*)addr, __float_as_int(v));
    else           atomicMin((unsigned int*)addr, __float_as_uint(v));
}

__device__ __forceinline__ unsigned su(const void* p) {
    return (unsigned)__cvta_generic_to_shared(p);
}
__device__ __forceinline__ void ldm4(unsigned* r, unsigned a) {
    asm volatile("ldmatrix.sync.aligned.m8n8.x4.shared.b16 {%0,%1,%2,%3},[%4];"
        : "=r"(r[0]), "=r"(r[1]), "=r"(r[2]), "=r"(r[3]) : "r"(a));
}
__device__ __forceinline__ void mma16816(float* c, const unsigned* a, const unsigned* b) {
    asm volatile("mma.sync.aligned.m16n8k16.row.col.f32.bf16.bf16.f32 "
        "{%0,%1,%2,%3},{%4,%5,%6,%7},{%8,%9},{%0,%1,%2,%3};"
        : "+f"(c[0]), "+f"(c[1]), "+f"(c[2]), "+f"(c[3])
        : "r"(a[0]), "r"(a[1]), "r"(a[2]), "r"(a[3]), "r"(b[0]), "r"(b[1]));
}

// ---------------- hi/lo split conversion ----------------
__global__ void cvt_hl(const float* __restrict__ src, __nv_bfloat16* __restrict__ hi,
                       __nv_bfloat16* __restrict__ lo, int n)
{
    int i = blockIdx.x * 256 + threadIdx.x;
    if (i < n) {
        float v = src[i];
        __nv_bfloat16 h = __float2bfloat16(v);
        hi[i] = h;
        lo[i] = __float2bfloat16(v - __bfloat162float(h));
    }
}

// ---------------- split-bf16 tensor GEMM ----------------
// C[M x 768] = A[M x K] @ W[768 x K]^T + bias, with A/W each split hi+lo bf16.
// D = Ahi*Whi + Alo*Whi + Ahi*Wlo  (fp32 accum). Block 128x64, BK=32, 8 warps.
template <int K>
__global__ __launch_bounds__(256, 2) void gemm_mma768(
    const __nv_bfloat16* __restrict__ Ahi, const __nv_bfloat16* __restrict__ Alo,
    const __nv_bfloat16* __restrict__ Bhi, const __nv_bfloat16* __restrict__ Blo,
    const float* __restrict__ bias, float* __restrict__ C, int M)
{
    __shared__ __align__(16) __nv_bfloat16 sAh[128 * LDT], sAl[128 * LDT];
    __shared__ __align__(16) __nv_bfloat16 sBh[64 * LDT],  sBl[64 * LDT];

    const int tid = threadIdx.x;
    const int rowBase = blockIdx.y * 128;
    const int colBase = blockIdx.x * 64;

    // global loaders
    const int arow = tid >> 1, akc = (tid & 1) * 16;   // A: 128 rows x 32 k
    const int brow = tid >> 2, bkc = (tid & 3) * 8;    // B: 64 rows x 32 k
    const int gar = rowBase + arow;
    const bool aval = gar < M;
    const size_t aoff = (size_t)(aval ? gar : 0) * K;
    const uint4* gAh = (const uint4*)(Ahi + aoff);
    const uint4* gAl = (const uint4*)(Alo + aoff);
    const uint4* gBh = (const uint4*)(Bhi + (size_t)(colBase + brow) * K);
    const uint4* gBl = (const uint4*)(Blo + (size_t)(colBase + brow) * K);

    // warp tiling: 4 warps over M (32 each), 2 over N (32 each)
    const int wid = tid >> 5, lane = tid & 31;
    const int warp_m = (wid & 3) * 32, warp_n = (wid >> 2) * 32;

    // ldmatrix base addresses (bytes)
    const unsigned aAh = su(&sAh[(warp_m + (lane & 15)) * LDT + (lane >> 4) * 8]);
    const unsigned aAl = su(&sAl[(warp_m + (lane & 15)) * LDT + (lane >> 4) * 8]);
    const int brr = warp_n + ((lane >> 4) * 8) + (lane & 7);
    const int bcc = ((lane >> 3) & 1) * 8;
    const unsigned aBh = su(&sBh[brr * LDT + bcc]);
    const unsigned aBl = su(&sBl[brr * LDT + bcc]);

    float acc[2][4][4];
#pragma unroll
    for (int i = 0; i < 2; i++)
#pragma unroll
        for (int j = 0; j < 4; j++)
#pragma unroll
            for (int k = 0; k < 4; k++) acc[i][j][k] = 0.0f;

    // register-buffered global loads
    uint4 rah0, rah1, ral0, ral1, rbh, rbl;
    {
        int ai = akc >> 3;
        if (aval) { rah0 = gAh[ai]; rah1 = gAh[ai + 1]; ral0 = gAl[ai]; ral1 = gAl[ai + 1]; }
        else { rah0 = rah1 = ral0 = ral1 = make_uint4(0, 0, 0, 0); }
        int bi = bkc >> 3;
        rbh = gBh[bi]; rbl = gBl[bi];
    }

#pragma unroll 1
    for (int k0 = 0; k0 < K; k0 += 32) {
        // commit current regs to smem
        *(uint4*)&sAh[arow * LDT + akc]     = rah0;
        *(uint4*)&sAh[arow * LDT + akc + 8] = rah1;
        *(uint4*)&sAl[arow * LDT + akc]     = ral0;
        *(uint4*)&sAl[arow * LDT + akc + 8] = ral1;
        *(uint4*)&sBh[brow * LDT + bkc]     = rbh;
        *(uint4*)&sBl[brow * LDT + bkc]     = rbl;
        __syncthreads();
        // prefetch next stage
        if (k0 + 32 < K) {
            int ai = (k0 + 32 + akc) >> 3;
            if (aval) { rah0 = gAh[ai]; rah1 = gAh[ai + 1]; ral0 = gAl[ai]; ral1 = gAl[ai + 1]; }
            int bi = (k0 + 32 + bkc) >> 3;
            rbh = gBh[bi]; rbl = gBl[bi];
        }
        // compute
#pragma unroll
        for (int kk = 0; kk < 32; kk += 16) {
            unsigned afh[2][4], afl[2][4], bfh[2][4], bfl[2][4];
            ldm4(afh[0], aAh + kk * 2);
            ldm4(afh[1], aAh + kk * 2 + 16 * LDT * 2);
            ldm4(afl[0], aAl + kk * 2);
            ldm4(afl[1], aAl + kk * 2 + 16 * LDT * 2);
            ldm4(bfh[0], aBh + kk * 2);
            ldm4(bfh[1], aBh + kk * 2 + 16 * LDT * 2);
            ldm4(bfl[0], aBl + kk * 2);
            ldm4(bfl[1], aBl + kk * 2 + 16 * LDT * 2);
#pragma unroll
            for (int mt = 0; mt < 2; mt++)
#pragma unroll
                for (int nb = 0; nb < 2; nb++) {
                    mma16816(acc[mt][nb * 2],     afh[mt], &bfh[nb][0]);
                    mma16816(acc[mt][nb * 2 + 1], afh[mt], &bfh[nb][2]);
                    mma16816(acc[mt][nb * 2],     afl[mt], &bfh[nb][0]);
                    mma16816(acc[mt][nb * 2 + 1], afl[mt], &bfh[nb][2]);
                    mma16816(acc[mt][nb * 2],     afh[mt], &bfl[nb][0]);
                    mma16816(acc[mt][nb * 2 + 1], afh[mt], &bfl[nb][2]);
                }
        }
        __syncthreads();
    }

    // epilogue
    const int g = lane >> 2, qp = (lane & 3) * 2;
#pragma unroll
    for (int mt = 0; mt < 2; mt++) {
        int r0 = rowBase + warp_m + mt * 16 + g;
#pragma unroll
        for (int nt = 0; nt < 4; nt++) {
            int col = colBase + warp_n + nt * 8 + qp;
            float b0 = bias[col], b1 = bias[col + 1];
            if (r0 < M) {
                float* p = &C[(size_t)r0 * G3 + col];
                p[0] = acc[mt][nt][0] + b0; p[1] = acc[mt][nt][1] + b1;
            }
            if (r0 + 8 < M) {
                float* p = &C[(size_t)(r0 + 8) * G3 + col];
                p[0] = acc[mt][nt][2] + b0; p[1] = acc[mt][nt][3] + b1;
            }
        }
    }
}

// ---------------- per-node first-step hidden (h0 = 0) ----------------
__global__ void h1_kernel(const float* __restrict__ gif, const float* __restrict__ gib,
                          const float* __restrict__ bhf, const float* __restrict__ bhb,
                          float* __restrict__ h1f, float* __restrict__ h1b)
{
    int n = blockIdx.x, t = threadIdx.x;
    size_t g = (size_t)n * G3;
    {
        float r  = sigf(gif[g + t]       + bhf[t]);
        float z  = sigf(gif[g + 256 + t] + bhf[256 + t]);
        float nn = tanhf(gif[g + 512 + t] + r * bhf[512 + t]);
        h1f[(size_t)n * HID + t] = (1.0f - z) * nn;
    }
    {
        float r  = sigf(gib[g + t]       + bhb[t]);
        float z  = sigf(gib[g + 256 + t] + bhb[256 + t]);
        float nn = tanhf(gib[g + 512 + t] + r * bhb[512 + t]);
        h1b[(size_t)n * HID + t] = (1.0f - z) * nn;
    }
}

// ---------------- gather initial hidden per edge (+ hi/lo split) ----------------
__global__ void hinit_kernel(float* __restrict__ H, __nv_bfloat16* __restrict__ Hhi,
                             __nv_bfloat16* __restrict__ Hlo,
                             const float* __restrict__ h1,
                             const int* __restrict__ emi, int col)
{
    int e = blockIdx.x, t = threadIdx.x;
    int node = emi[e * 4 + col];
    float v = h1[(size_t)node * HID + t];
    size_t i = (size_t)e * HID + t;
    H[i] = v;
    __nv_bfloat16 h = __float2bfloat16(v);
    Hhi[i] = h;
    Hlo[i] = __float2bfloat16(v - __bfloat162float(h));
}

// ---------------- GRU pointwise step (+ hi/lo split of new h) ----------------
__global__ void gru_step(float* __restrict__ H, __nv_bfloat16* __restrict__ Hhi,
                         __nv_bfloat16* __restrict__ Hlo,
                         const float* __restrict__ GH, const float* __restrict__ GI,
                         const int* __restrict__ emi, int col)
{
    int e = blockIdx.x, t = threadIdx.x;
    int node = emi[e * 4 + col];
    size_t ge = (size_t)e * G3, gn = (size_t)node * G3;
    float r  = sigf(GI[gn + t]       + GH[ge + t]);
    float z  = sigf(GI[gn + 256 + t] + GH[ge + 256 + t]);
    float nn = tanhf(GI[gn + 512 + t] + r * GH[ge + 512 + t]);
    size_t hi = (size_t)e * HID + t;
    float h = H[hi];
    float hnew = (1.0f - z) * nn + z * h;
    H[hi] = hnew;
    __nv_bfloat16 bh = __float2bfloat16(hnew);
    Hhi[hi] = bh;
    Hlo[hi] = __float2bfloat16(hnew - __bfloat162float(bh));
}

// ---------------- init segment max / denom ----------------
__global__ void init_md(float* __restrict__ Mmax, float* __restrict__ Den)
{
    int i = blockIdx.x * 256 + threadIdx.x;
    Mmax[i] = __int_as_float(0xFF800000);
    Den[i] = 0.0f;
}

// ---------------- attention logits + leaky relu + segment max ----------------
__global__ void attn_kernel(const float* __restrict__ Hf, const float* __restrict__ Hb,
                            const float* __restrict__ attn, const int* __restrict__ dst,
                            float* __restrict__ Alog, float* __restrict__ Mmax)
{
    __shared__ float at[512];
    int tid = threadIdx.x;
    at[tid] = attn[tid];
    at[tid + 256] = attn[tid + 256];
    __syncthreads();

    int eL = tid >> 3, h = tid & 7;
    int e = blockIdx.x * 32 + eL;
    const float* hf = Hf + (size_t)e * HID;
    const float* hb = Hb + (size_t)e * HID;
    float acc = 0.0f;
#pragma unroll
    for (int d = 0; d < 32; d++) acc += hf[d * 8 + h] * at[h * 64 + d];
#pragma unroll
    for (int d = 0; d < 32; d++) acc += hb[d * 8 + h] * at[h * 64 + 32 + d];
    float a = (acc >= 0.0f) ? acc : 0.01f * acc;
    Alog[(size_t)e * NH + h] = a;
    atomicMaxFloat(&Mmax[(size_t)dst[e] * NH + h], a);
}

// ---------------- exp + segment denom ----------------
__global__ void expden_kernel(const int* __restrict__ dst, float* __restrict__ Alog,
                              const float* __restrict__ Mmax, float* __restrict__ Den)
{
    int i = blockIdx.x * 256 + threadIdx.x;
    int e = i >> 3, h = i & 7;
    int d = dst[e];
    float ex = __expf(Alog[i] - Mmax[(size_t)d * NH + h]);
    Alog[i] = ex;
    atomicAdd(&Den[(size_t)d * NH + h], ex);
}

// ---------------- weighted scatter into destination nodes ----------------
__global__ void scatter_kernel(const float* __restrict__ Hf, const float* __restrict__ Hb,
                               const float* __restrict__ Alog, const float* __restrict__ Den,
                               const int* __restrict__ dst, float* __restrict__ out)
{
    int warp = threadIdx.x >> 5, lane = threadIdx.x & 31;
    int e = blockIdx.x * 8 + warp;
    int h = lane >> 2;
    int dq = (lane & 3) << 4;
    int dn = dst[e];
    float w = Alog[(size_t)e * NH + h] / Den[(size_t)dn * NH + h];
    float* ob = out + (size_t)dn * (NH * ODIM) + h * ODIM + dq;
    const float* src = (dq < 32)
        ? (Hf + (size_t)e * HID + dq * 8 + h)
        : (Hb + (size_t)e * HID + (dq - 32) * 8 + h);
#pragma unroll
    for (int i = 0; i < 16; i++) atomicAdd(ob + i, src[i * 8] * w);
}

// ---------------- launch ----------------
extern "C" void kernel_launch(void* const* d_in, const int* in_sizes, int n_in,
                              void* d_out, int out_size)
{
    const float* features = (const float*)d_in[0];
    const float* w_ih_f   = (const float*)d_in[1];
    const float* w_hh_f   = (const float*)d_in[2];
    const float* b_ih_f   = (const float*)d_in[3];
    const float* b_hh_f   = (const float*)d_in[4];
    const float* w_ih_b   = (const float*)d_in[5];
    const float* w_hh_b   = (const float*)d_in[6];
    const float* b_ih_b   = (const float*)d_in[7];
    const float* b_hh_b   = (const float*)d_in[8];
    const float* attn     = (const float*)d_in[9];
    const int*   emi      = (const int*)d_in[10];
    const int*   edst     = (const int*)d_in[11];
    float* out = (float*)d_out;

    float *gif, *gib, *h1f, *h1b, *Hf, *Hb, *GH, *Alog, *Mmax, *Den;
    __nv_bfloat16 *Hhi, *Hlo, *Fhi, *Flo;
    __nv_bfloat16 *WihfHi, *WihfLo, *WihbHi, *WihbLo;
    __nv_bfloat16 *WhhfHi, *WhhfLo, *WhhbHi, *WhhbLo;
    cudaGetSymbolAddress((void**)&gif,  d_gif);
    cudaGetSymbolAddress((void**)&gib,  d_gib);
    cudaGetSymbolAddress((void**)&h1f,  d_h1f);
    cudaGetSymbolAddress((void**)&h1b,  d_h1b);
    cudaGetSymbolAddress((void**)&Hf,   d_Hf);
    cudaGetSymbolAddress((void**)&Hb,   d_Hb);
    cudaGetSymbolAddress((void**)&GH,   d_GH);
    cudaGetSymbolAddress((void**)&Alog, d_Alog);
    cudaGetSymbolAddress((void**)&Mmax, d_Mmax);
    cudaGetSymbolAddress((void**)&Den,  d_Den);
    cudaGetSymbolAddress((void**)&Hhi,  d_Hhi);
    cudaGetSymbolAddress((void**)&Hlo,  d_Hlo);
    cudaGetSymbolAddress((void**)&Fhi,  d_Fhi);
    cudaGetSymbolAddress((void**)&Flo,  d_Flo);
    cudaGetSymbolAddress((void**)&WihfHi, d_WihfHi);
    cudaGetSymbolAddress((void**)&WihfLo, d_WihfLo);
    cudaGetSymbolAddress((void**)&WihbHi, d_WihbHi);
    cudaGetSymbolAddress((void**)&WihbLo, d_WihbLo);
    cudaGetSymbolAddress((void**)&WhhfHi, d_WhhfHi);
    cudaGetSymbolAddress((void**)&WhhfLo, d_WhhfLo);
    cudaGetSymbolAddress((void**)&WhhbHi, d_WhhbHi);
    cudaGetSymbolAddress((void**)&WhhbLo, d_WhhbLo);

    cudaMemsetAsync(d_out, 0, (size_t)out_size * sizeof(float), 0);
    init_md<<<(NNODE * NH) / 256, 256>>>(Mmax, Den);

    // hi/lo splits of static operands
    cvt_hl<<<(NNODE * ODIM + 255) / 256, 256>>>(features, Fhi, Flo, NNODE * ODIM);
    cvt_hl<<<(G3 * ODIM + 255) / 256, 256>>>(w_ih_f, WihfHi, WihfLo, G3 * ODIM);
    cvt_hl<<<(G3 * ODIM + 255) / 256, 256>>>(w_ih_b, WihbHi, WihbLo, G3 * ODIM);
    cvt_hl<<<(G3 * HID + 255) / 256, 256>>>(w_hh_f, WhhfHi, WhhfLo, G3 * HID);
    cvt_hl<<<(G3 * HID + 255) / 256, 256>>>(w_hh_b, WhhbHi, WhhbLo, G3 * HID);

    // per-node gi (input transform + b_ih) and first-step hidden
    dim3 gn(G3 / 64, (NNODE + 127) / 128);
    gemm_mma768<ODIM><<<gn, 256>>>(Fhi, Flo, WihfHi, WihfLo, b_ih_f, gif, NNODE);
    gemm_mma768<ODIM><<<gn, 256>>>(Fhi, Flo, WihbHi, WihbLo, b_ih_b, gib, NNODE);
    h1_kernel<<<NNODE, 256>>>(gif, gib, b_hh_f, b_hh_b, h1f, h1b);

    dim3 ge(G3 / 64, (NEDGE + 127) / 128);

    // forward direction: metapath cols 0..3 (step 1 precomputed per node)
    hinit_kernel<<<NEDGE, 256>>>(Hf, Hhi, Hlo, h1f, emi, 0);
    for (int t = 1; t <= 3; t++) {
        gemm_mma768<HID><<<ge, 256>>>(Hhi, Hlo, WhhfHi, WhhfLo, b_hh_f, GH, NEDGE);
        gru_step<<<NEDGE, 256>>>(Hf, Hhi, Hlo, GH, gif, emi, t);
    }

    // backward direction: cols 3,2,1,0 (step 1 precomputed from col 3)
    hinit_kernel<<<NEDGE, 256>>>(Hb, Hhi, Hlo, h1b, emi, 3);
    const int bcols[3] = {2, 1, 0};
    for (int t = 0; t < 3; t++) {
        gemm_mma768<HID><<<ge, 256>>>(Hhi, Hlo, WhhbHi, WhhbLo, b_hh_b, GH, NEDGE);
        gru_step<<<NEDGE, 256>>>(Hb, Hhi, Hlo, GH, gib, emi, bcols[t]);
    }

    // attention + segment softmax + scatter
    attn_kernel<<<NEDGE / 32, 256>>>(Hf, Hb, attn, edst, Alog, Mmax);
    expden_kernel<<<(NEDGE * NH) / 256, 256>>>(edst, Alog, Mmax, Den);
    scatter_kernel<<<NEDGE / 8, 256>>>(Hf, Hb, Alog, Den, edst, out);
}

// round 17
// speedup vs baseline: 1.7579x; 1.0003x over previous
#include <cuda_runtime.h>
#include <cuda_bf16.h>

// ---------------- problem constants ----------------
#define NNODE 100000
#define NEDGE 500000
#define G3    768     // 3 * HID
#define HID   256
#define NH    8
#define ODIM  64
#define LDT   40      // smem row stride (bf16 elems): 80B -> conflict-free LDSM

// ---------------- device scratch ----------------
__device__ float d_gif[(size_t)NNODE * G3];
__device__ float d_gib[(size_t)NNODE * G3];
__device__ float d_h1f[(size_t)NNODE * HID];
__device__ float d_h1b[(size_t)NNODE * HID];
__device__ float d_Hf[(size_t)NEDGE * HID];
__device__ float d_Hb[(size_t)NEDGE * HID];
__device__ float d_GH[(size_t)NEDGE * G3];
__device__ float d_Alog[(size_t)NEDGE * NH];
__device__ float d_Mmax[(size_t)NNODE * NH];
__device__ float d_Den[(size_t)NNODE * NH];
// split-bf16 operands
__device__ __nv_bfloat16 d_Hhi[(size_t)NEDGE * HID];
__device__ __nv_bfloat16 d_Hlo[(size_t)NEDGE * HID];
__device__ __nv_bfloat16 d_Fhi[(size_t)NNODE * ODIM];
__device__ __nv_bfloat16 d_Flo[(size_t)NNODE * ODIM];
__device__ __nv_bfloat16 d_WihfHi[G3 * ODIM], d_WihfLo[G3 * ODIM];
__device__ __nv_bfloat16 d_WihbHi[G3 * ODIM], d_WihbLo[G3 * ODIM];
__device__ __nv_bfloat16 d_WhhfHi[G3 * HID], d_WhhfLo[G3 * HID];
__device__ __nv_bfloat16 d_WhhbHi[G3 * HID], d_WhhbLo[G3 * HID];

// ---------------- helpers ----------------
__device__ __forceinline__ float sigf(float x) { return 1.0f / (1.0f + __expf(-x)); }

__device__ __forceinline__ void atomicMaxFloat(float* addr, float v) {
    if (v >= 0.0f) atomicMax((int*)addr, __float_as_int(v));
    else           atomicMin((unsigned int*)addr, __float_as_uint(v));
}

__device__ __forceinline__ unsigned su(const void* p) {
    return (unsigned)__cvta_generic_to_shared(p);
}
__device__ __forceinline__ void ldm4(unsigned* r, unsigned a) {
    asm volatile("ldmatrix.sync.aligned.m8n8.x4.shared.b16 {%0,%1,%2,%3},[%4];"
        : "=r"(r[0]), "=r"(r[1]), "=r"(r[2]), "=r"(r[3]) : "r"(a));
}
__device__ __forceinline__ void mma16816(float* c, const unsigned* a, const unsigned* b) {
    asm volatile("mma.sync.aligned.m16n8k16.row.col.f32.bf16.bf16.f32 "
        "{%0,%1,%2,%3},{%4,%5,%6,%7},{%8,%9},{%0,%1,%2,%3};"
        : "+f"(c[0]), "+f"(c[1]), "+f"(c[2]), "+f"(c[3])
        : "r"(a[0]), "r"(a[1]), "r"(a[2]), "r"(a[3]), "r"(b[0]), "r"(b[1]));
}

// ---------------- hi/lo split conversion ----------------
__global__ void cvt_hl(const float* __restrict__ src, __nv_bfloat16* __restrict__ hi,
                       __nv_bfloat16* __restrict__ lo, int n)
{
    int i = blockIdx.x * 256 + threadIdx.x;
    if (i < n) {
        float v = src[i];
        __nv_bfloat16 h = __float2bfloat16(v);
        hi[i] = h;
        lo[i] = __float2bfloat16(v - __bfloat162float(h));
    }
}

// ---------------- split-bf16 tensor GEMM ----------------
// C[M x 768] = A[M x K] @ W[768 x K]^T + bias, with A/W each split hi+lo bf16.
// D = Ahi*Whi + Alo*Whi + Ahi*Wlo  (fp32 accum). Block 128x64, BK=32, 8 warps.
template <int K>
__global__ __launch_bounds__(256, 2) void gemm_mma768(
    const __nv_bfloat16* __restrict__ Ahi, const __nv_bfloat16* __restrict__ Alo,
    const __nv_bfloat16* __restrict__ Bhi, const __nv_bfloat16* __restrict__ Blo,
    const float* __restrict__ bias, float* __restrict__ C, int M)
{
    __shared__ __align__(16) __nv_bfloat16 sAh[128 * LDT], sAl[128 * LDT];
    __shared__ __align__(16) __nv_bfloat16 sBh[64 * LDT],  sBl[64 * LDT];

    const int tid = threadIdx.x;
    const int rowBase = blockIdx.y * 128;
    const int colBase = blockIdx.x * 64;

    // global loaders
    const int arow = tid >> 1, akc = (tid & 1) * 16;   // A: 128 rows x 32 k
    const int brow = tid >> 2, bkc = (tid & 3) * 8;    // B: 64 rows x 32 k
    const int gar = rowBase + arow;
    const bool aval = gar < M;
    const size_t aoff = (size_t)(aval ? gar : 0) * K;
    const uint4* gAh = (const uint4*)(Ahi + aoff);
    const uint4* gAl = (const uint4*)(Alo + aoff);
    const uint4* gBh = (const uint4*)(Bhi + (size_t)(colBase + brow) * K);
    const uint4* gBl = (const uint4*)(Blo + (size_t)(colBase + brow) * K);

    // warp tiling: 4 warps over M (32 each), 2 over N (32 each)
    const int wid = tid >> 5, lane = tid & 31;
    const int warp_m = (wid & 3) * 32, warp_n = (wid >> 2) * 32;

    // ldmatrix base addresses (bytes)
    const unsigned aAh = su(&sAh[(warp_m + (lane & 15)) * LDT + (lane >> 4) * 8]);
    const unsigned aAl = su(&sAl[(warp_m + (lane & 15)) * LDT + (lane >> 4) * 8]);
    const int brr = warp_n + ((lane >> 4) * 8) + (lane & 7);
    const int bcc = ((lane >> 3) & 1) * 8;
    const unsigned aBh = su(&sBh[brr * LDT + bcc]);
    const unsigned aBl = su(&sBl[brr * LDT + bcc]);

    float acc[2][4][4];
#pragma unroll
    for (int i = 0; i < 2; i++)
#pragma unroll
        for (int j = 0; j < 4; j++)
#pragma unroll
            for (int k = 0; k < 4; k++) acc[i][j][k] = 0.0f;

    // register-buffered global loads
    uint4 rah0, rah1, ral0, ral1, rbh, rbl;
    {
        int ai = akc >> 3;
        if (aval) { rah0 = gAh[ai]; rah1 = gAh[ai + 1]; ral0 = gAl[ai]; ral1 = gAl[ai + 1]; }
        else { rah0 = rah1 = ral0 = ral1 = make_uint4(0, 0, 0, 0); }
        int bi = bkc >> 3;
        rbh = gBh[bi]; rbl = gBl[bi];
    }

#pragma unroll 1
    for (int k0 = 0; k0 < K; k0 += 32) {
        // commit current regs to smem
        *(uint4*)&sAh[arow * LDT + akc]     = rah0;
        *(uint4*)&sAh[arow * LDT + akc + 8] = rah1;
        *(uint4*)&sAl[arow * LDT + akc]     = ral0;
        *(uint4*)&sAl[arow * LDT + akc + 8] = ral1;
        *(uint4*)&sBh[brow * LDT + bkc]     = rbh;
        *(uint4*)&sBl[brow * LDT + bkc]     = rbl;
        __syncthreads();
        // prefetch next stage
        if (k0 + 32 < K) {
            int ai = (k0 + 32 + akc) >> 3;
            if (aval) { rah0 = gAh[ai]; rah1 = gAh[ai + 1]; ral0 = gAl[ai]; ral1 = gAl[ai + 1]; }
            int bi = (k0 + 32 + bkc) >> 3;
            rbh = gBh[bi]; rbl = gBl[bi];
        }
        // compute
#pragma unroll
        for (int kk = 0; kk < 32; kk += 16) {
            unsigned afh[2][4], afl[2][4], bfh[2][4], bfl[2][4];
            ldm4(afh[0], aAh + kk * 2);
            ldm4(afh[1], aAh + kk * 2 + 16 * LDT * 2);
            ldm4(afl[0], aAl + kk * 2);
            ldm4(afl[1], aAl + kk * 2 + 16 * LDT * 2);
            ldm4(bfh[0], aBh + kk * 2);
            ldm4(bfh[1], aBh + kk * 2 + 16 * LDT * 2);
            ldm4(bfl[0], aBl + kk * 2);
            ldm4(bfl[1], aBl + kk * 2 + 16 * LDT * 2);
#pragma unroll
            for (int mt = 0; mt < 2; mt++)
#pragma unroll
                for (int nb = 0; nb < 2; nb++) {
                    mma16816(acc[mt][nb * 2],     afh[mt], &bfh[nb][0]);
                    mma16816(acc[mt][nb * 2 + 1], afh[mt], &bfh[nb][2]);
                    mma16816(acc[mt][nb * 2],     afl[mt], &bfh[nb][0]);
                    mma16816(acc[mt][nb * 2 + 1], afl[mt], &bfh[nb][2]);
                    mma16816(acc[mt][nb * 2],     afh[mt], &bfl[nb][0]);
                    mma16816(acc[mt][nb * 2 + 1], afh[mt], &bfl[nb][2]);
                }
        }
        __syncthreads();
    }

    // epilogue
    const int g = lane >> 2, qp = (lane & 3) * 2;
#pragma unroll
    for (int mt = 0; mt < 2; mt++) {
        int r0 = rowBase + warp_m + mt * 16 + g;
#pragma unroll
        for (int nt = 0; nt < 4; nt++) {
            int col = colBase + warp_n + nt * 8 + qp;
            float b0 = bias[col], b1 = bias[col + 1];
            if (r0 < M) {
                float* p = &C[(size_t)r0 * G3 + col];
                p[0] = acc[mt][nt][0] + b0; p[1] = acc[mt][nt][1] + b1;
            }
            if (r0 + 8 < M) {
                float* p = &C[(size_t)(r0 + 8) * G3 + col];
                p[0] = acc[mt][nt][2] + b0; p[1] = acc[mt][nt][3] + b1;
            }
        }
    }
}

// ---------------- per-node first-step hidden (h0 = 0) ----------------
__global__ void h1_kernel(const float* __restrict__ gif, const float* __restrict__ gib,
                          const float* __restrict__ bhf, const float* __restrict__ bhb,
                          float* __restrict__ h1f, float* __restrict__ h1b)
{
    int n = blockIdx.x, t = threadIdx.x;
    size_t g = (size_t)n * G3;
    {
        float r  = sigf(gif[g + t]       + bhf[t]);
        float z  = sigf(gif[g + 256 + t] + bhf[256 + t]);
        float nn = tanhf(gif[g + 512 + t] + r * bhf[512 + t]);
        h1f[(size_t)n * HID + t] = (1.0f - z) * nn;
    }
    {
        float r  = sigf(gib[g + t]       + bhb[t]);
        float z  = sigf(gib[g + 256 + t] + bhb[256 + t]);
        float nn = tanhf(gib[g + 512 + t] + r * bhb[512 + t]);
        h1b[(size_t)n * HID + t] = (1.0f - z) * nn;
    }
}

// ---------------- gather initial hidden per edge (+ hi/lo split) ----------------
__global__ void hinit_kernel(float* __restrict__ H, __nv_bfloat16* __restrict__ Hhi,
                             __nv_bfloat16* __restrict__ Hlo,
                             const float* __restrict__ h1,
                             const int* __restrict__ emi, int col)
{
    int e = blockIdx.x, t = threadIdx.x;
    int node = emi[e * 4 + col];
    float v = h1[(size_t)node * HID + t];
    size_t i = (size_t)e * HID + t;
    H[i] = v;
    __nv_bfloat16 h = __float2bfloat16(v);
    Hhi[i] = h;
    Hlo[i] = __float2bfloat16(v - __bfloat162float(h));
}

// ---------------- GRU pointwise step (+ hi/lo split of new h) ----------------
__global__ void gru_step(float* __restrict__ H, __nv_bfloat16* __restrict__ Hhi,
                         __nv_bfloat16* __restrict__ Hlo,
                         const float* __restrict__ GH, const float* __restrict__ GI,
                         const int* __restrict__ emi, int col)
{
    int e = blockIdx.x, t = threadIdx.x;
    int node = emi[e * 4 + col];
    size_t ge = (size_t)e * G3, gn = (size_t)node * G3;
    float r  = sigf(GI[gn + t]       + GH[ge + t]);
    float z  = sigf(GI[gn + 256 + t] + GH[ge + 256 + t]);
    float nn = tanhf(GI[gn + 512 + t] + r * GH[ge + 512 + t]);
    size_t hi = (size_t)e * HID + t;
    float h = H[hi];
    float hnew = (1.0f - z) * nn + z * h;
    H[hi] = hnew;
    __nv_bfloat16 bh = __float2bfloat16(hnew);
    Hhi[hi] = bh;
    Hlo[hi] = __float2bfloat16(hnew - __bfloat162float(bh));
}

// ---------------- init segment max / denom ----------------
__global__ void init_md(float* __restrict__ Mmax, float* __restrict__ Den)
{
    int i = blockIdx.x * 256 + threadIdx.x;
    Mmax[i] = __int_as_float(0xFF800000);
    Den[i] = 0.0f;
}

// ---------------- attention logits + leaky relu + segment max ----------------
__global__ void attn_kernel(const float* __restrict__ Hf, const float* __restrict__ Hb,
                            const float* __restrict__ attn, const int* __restrict__ dst,
                            float* __restrict__ Alog, float* __restrict__ Mmax)
{
    __shared__ float at[512];
    int tid = threadIdx.x;
    at[tid] = attn[tid];
    at[tid + 256] = attn[tid + 256];
    __syncthreads();

    int eL = tid >> 3, h = tid & 7;
    int e = blockIdx.x * 32 + eL;
    const float* hf = Hf + (size_t)e * HID;
    const float* hb = Hb + (size_t)e * HID;
    float acc = 0.0f;
#pragma unroll
    for (int d = 0; d < 32; d++) acc += hf[d * 8 + h] * at[h * 64 + d];
#pragma unroll
    for (int d = 0; d < 32; d++) acc += hb[d * 8 + h] * at[h * 64 + 32 + d];
    float a = (acc >= 0.0f) ? acc : 0.01f * acc;
    Alog[(size_t)e * NH + h] = a;
    atomicMaxFloat(&Mmax[(size_t)dst[e] * NH + h], a);
}

// ---------------- exp + segment denom ----------------
__global__ void expden_kernel(const int* __restrict__ dst, float* __restrict__ Alog,
                              const float* __restrict__ Mmax, float* __restrict__ Den)
{
    int i = blockIdx.x * 256 + threadIdx.x;
    int e = i >> 3, h = i & 7;
    int d = dst[e];
    float ex = __expf(Alog[i] - Mmax[(size_t)d * NH + h]);
    Alog[i] = ex;
    atomicAdd(&Den[(size_t)d * NH + h], ex);
}

// ---------------- weighted scatter into destination nodes ----------------
__global__ void scatter_kernel(const float* __restrict__ Hf, const float* __restrict__ Hb,
                               const float* __restrict__ Alog, const float* __restrict__ Den,
                               const int* __restrict__ dst, float* __restrict__ out)
{
    int warp = threadIdx.x >> 5, lane = threadIdx.x & 31;
    int e = blockIdx.x * 8 + warp;
    int h = lane >> 2;
    int dq = (lane & 3) << 4;
    int dn = dst[e];
    float w = Alog[(size_t)e * NH + h] / Den[(size_t)dn * NH + h];
    float* ob = out + (size_t)dn * (NH * ODIM) + h * ODIM + dq;
    const float* src = (dq < 32)
        ? (Hf + (size_t)e * HID + dq * 8 + h)
        : (Hb + (size_t)e * HID + (dq - 32) * 8 + h);
#pragma unroll
    for (int i = 0; i < 16; i++) atomicAdd(ob + i, src[i * 8] * w);
}

// ---------------- launch ----------------
extern "C" void kernel_launch(void* const* d_in, const int* in_sizes, int n_in,
                              void* d_out, int out_size)
{
    const float* features = (const float*)d_in[0];
    const float* w_ih_f   = (const float*)d_in[1];
    const float* w_hh_f   = (const float*)d_in[2];
    const float* b_ih_f   = (const float*)d_in[3];
    const float* b_hh_f   = (const float*)d_in[4];
    const float* w_ih_b   = (const float*)d_in[5];
    const float* w_hh_b   = (const float*)d_in[6];
    const float* b_ih_b   = (const float*)d_in[7];
    const float* b_hh_b   = (const float*)d_in[8];
    const float* attn     = (const float*)d_in[9];
    const int*   emi      = (const int*)d_in[10];
    const int*   edst     = (const int*)d_in[11];
    float* out = (float*)d_out;

    float *gif, *gib, *h1f, *h1b, *Hf, *Hb, *GH, *Alog, *Mmax, *Den;
    __nv_bfloat16 *Hhi, *Hlo, *Fhi, *Flo;
    __nv_bfloat16 *WihfHi, *WihfLo, *WihbHi, *WihbLo;
    __nv_bfloat16 *WhhfHi, *WhhfLo, *WhhbHi, *WhhbLo;
    cudaGetSymbolAddress((void**)&gif,  d_gif);
    cudaGetSymbolAddress((void**)&gib,  d_gib);
    cudaGetSymbolAddress((void**)&h1f,  d_h1f);
    cudaGetSymbolAddress((void**)&h1b,  d_h1b);
    cudaGetSymbolAddress((void**)&Hf,   d_Hf);
    cudaGetSymbolAddress((void**)&Hb,   d_Hb);
    cudaGetSymbolAddress((void**)&GH,   d_GH);
    cudaGetSymbolAddress((void**)&Alog, d_Alog);
    cudaGetSymbolAddress((void**)&Mmax, d_Mmax);
    cudaGetSymbolAddress((void**)&Den,  d_Den);
    cudaGetSymbolAddress((void**)&Hhi,  d_Hhi);
    cudaGetSymbolAddress((void**)&Hlo,  d_Hlo);
    cudaGetSymbolAddress((void**)&Fhi,  d_Fhi);
    cudaGetSymbolAddress((void**)&Flo,  d_Flo);
    cudaGetSymbolAddress((void**)&WihfHi, d_WihfHi);
    cudaGetSymbolAddress((void**)&WihfLo, d_WihfLo);
    cudaGetSymbolAddress((void**)&WihbHi, d_WihbHi);
    cudaGetSymbolAddress((void**)&WihbLo, d_WihbLo);
    cudaGetSymbolAddress((void**)&WhhfHi, d_WhhfHi);
    cudaGetSymbolAddress((void**)&WhhfLo, d_WhhfLo);
    cudaGetSymbolAddress((void**)&WhhbHi, d_WhhbHi);
    cudaGetSymbolAddress((void**)&WhhbLo, d_WhhbLo);

    cudaMemsetAsync(d_out, 0, (size_t)out_size * sizeof(float), 0);
    init_md<<<(NNODE * NH) / 256, 256>>>(Mmax, Den);

    // hi/lo splits of static operands
    cvt_hl<<<(NNODE * ODIM + 255) / 256, 256>>>(features, Fhi, Flo, NNODE * ODIM);
    cvt_hl<<<(G3 * ODIM + 255) / 256, 256>>>(w_ih_f, WihfHi, WihfLo, G3 * ODIM);
    cvt_hl<<<(G3 * ODIM + 255) / 256, 256>>>(w_ih_b, WihbHi, WihbLo, G3 * ODIM);
    cvt_hl<<<(G3 * HID + 255) / 256, 256>>>(w_hh_f, WhhfHi, WhhfLo, G3 * HID);
    cvt_hl<<<(G3 * HID + 255) / 256, 256>>>(w_hh_b, WhhbHi, WhhbLo, G3 * HID);

    // per-node gi (input transform + b_ih) and first-step hidden
    dim3 gn(G3 / 64, (NNODE + 127) / 128);
    gemm_mma768<ODIM><<<gn, 256>>>(Fhi, Flo, WihfHi, WihfLo, b_ih_f, gif, NNODE);
    gemm_mma768<ODIM><<<gn, 256>>>(Fhi, Flo, WihbHi, WihbLo, b_ih_b, gib, NNODE);
    h1_kernel<<<NNODE, 256>>>(gif, gib, b_hh_f, b_hh_b, h1f, h1b);

    dim3 ge(G3 / 64, (NEDGE + 127) / 128);

    // forward direction: metapath cols 0..3 (step 1 precomputed per node)
    hinit_kernel<<<NEDGE, 256>>>(Hf, Hhi, Hlo, h1f, emi, 0);
    for (int t = 1; t <= 3; t++) {
        gemm_mma768<HID><<<ge, 256>>>(Hhi, Hlo, WhhfHi, WhhfLo, b_hh_f, GH, NEDGE);
        gru_step<<<NEDGE, 256>>>(Hf, Hhi, Hlo, GH, gif, emi, t);
    }

    // backward direction: cols 3,2,1,0 (step 1 precomputed from col 3)
    hinit_kernel<<<NEDGE, 256>>>(Hb, Hhi, Hlo, h1b, emi, 3);
    const int bcols[3] = {2, 1, 0};
    for (int t = 0; t < 3; t++) {
        gemm_mma768<HID><<<ge, 256>>>(Hhi, Hlo, WhhbHi, WhhbLo, b_hh_b, GH, NEDGE);
        gru_step<<<NEDGE, 256>>>(Hb, Hhi, Hlo, GH, gib, emi, bcols[t]);
    }

    // attention + segment softmax + scatter
    attn_kernel<<<NEDGE / 32, 256>>>(Hf, Hb, attn, edst, Alog, Mmax);
    expden_kernel<<<(NEDGE * NH) / 256, 256>>>(edst, Alog, Mmax, Den);
    scatter_kernel<<<NEDGE / 8, 256>>>(Hf, Hb, Alog, Den, edst, out);
}